// round 5
// baseline (speedup 1.0000x reference)
#include <cuda_runtime.h>

// gnn_42460046688469 — Fourier-graph gather + complex weighted aggregate + permuted scatter.
//
// R5 change vs the 352us passing kernel: CACHE-POLICY ANNOTATIONS ONLY.
// The 134 MB gather table (Xf_real+Xf_imag) nearly fits the 126 MB L2, but the
// per-replay streams (output 67-134 MB stores, NI/w 50 MB, indices 6 MB) were
// evicting it, forcing ~1.2 GB of gather traffic to DRAM (measured 1.85 GB,
// DRAM 72.8% busy). Now all stream accesses are evict-first (__ldcs/__stcs)
// and only the Xf gathers allocate normally in L2, so the table stays
// resident across replays.
//
// Interface handling (unchanged, proven): content-based detection of operand
// order / index width / size units; every gathered index clamped; output
// layout (interleaved complex vs real-only) chosen from out_size with all
// stores bounded.

#define K_NB 8

struct Cfg { int u; int is64; int niSel; int imagFirst; };
__device__ Cfg g_cfg;

__global__ void detect_kernel(const unsigned* __restrict__ m0,
                              const unsigned* __restrict__ m1,
                              const unsigned* __restrict__ m2,
                              const unsigned* __restrict__ hind,
                              int s_mid, int s_hi)
{
    if (threadIdx.x != 0 || blockIdx.x != 0) return;

    int Wm = s_mid >> 2;   // words provably in-bounds under both unit schemes
    int Wh = s_hi >> 2;

    const unsigned* ms[3] = { m0, m1, m2 };
    int isInt[3];
    {
        int step = Wm / 67; if (step < 1) step = 1;
        for (int b = 0; b < 3; ++b) {
            int ok = 1;
            for (int j = 0; j < 64; ++j) {
                unsigned v = ms[b][(j * step + j) % Wm];
                if (v >= 0x01000000u) { ok = 0; break; }
            }
            isInt[b] = ok;
        }
    }
    int niSel = 2;
    if (isInt[0] && !isInt[2]) niSel = 0;
    else if (isInt[1] && !isInt[0] && !isInt[2]) niSel = 1;
    int imagFirst = (niSel == 0) ? 1 : 0;

    int zeros = 0;
    {
        int step = Wh / 67; if (step < 1) step = 1;
        for (int j = 0; j < 64; ++j) {
            int w = ((j * step + j) % Wh) | 1;
            if (hind[w] == 0u) zeros++;
        }
    }
    int is64 = (zeros >= 48) ? 1 : 0;

    unsigned vmax = 0;
    {
        int step = Wh / 67; if (step < 1) step = 1;
        for (int j = 0; j < 64; ++j) {
            int w = (j * step + j) % Wh;
            if (is64) w &= ~1;
            unsigned v = hind[w];
            if (v > vmax) vmax = v;
        }
    }
    unsigned thresh = is64 ? (unsigned)(s_hi >> 3) : (unsigned)(s_hi >> 2);
    int u = (vmax >= thresh) ? 1 : 4;

    Cfg c; c.u = u; c.is64 = is64; c.niSel = niSel; c.imagFirst = imagFirst;
    g_cfg = c;
}

// streaming (evict-first) index load
__device__ __forceinline__ int load_idx_cs(const void* p, int off, int is64) {
    return is64 ? (int)__ldcs((const long long*)p + off)
                : __ldcs((const int*)p + off);
}

__global__ void __launch_bounds__(256, 8) gnn_fourier_kernel(
    const float* __restrict__ xf0, const float* __restrict__ xf1,
    const void*  __restrict__ m0,  const void*  __restrict__ m1,
    const void*  __restrict__ m2,
    const void*  __restrict__ hmask, const void* __restrict__ hind,
    float4* __restrict__ out,
    int s_max, int s_mid, int s_hi, int s_hm, int out_count)
{
    Cfg c = g_cfg;

    int idxDiv = c.u * ((c.is64 && c.u == 4) ? 2 : 1);
    int NH     = s_hi / idxDiv;
    int H      = s_hm / idxDiv;
    int N      = (s_mid / c.u) / K_NB;
    int Mrows  = (s_max / c.u) / 16;

    int gid = blockIdx.x * blockDim.x + threadIdx.x;
    int row = gid >> 2;
    if (row >= NH) return;
    int t = gid & 3;

    const void* mids[3] = { m0, m1, m2 };
    const void* NIp = mids[c.niSel];
    const void* wa  = (c.niSel == 0) ? m1 : m0;
    const void* wb  = (c.niSel == 2) ? m1 : m2;
    const float* wR = (const float*)(c.imagFirst ? wb : wa);
    const float* wI = (const float*)(c.imagFirst ? wa : wb);
    const float4* XfR = (const float4*)(c.imagFirst ? xf1 : xf0);
    const float4* XfI = (const float4*)(c.imagFirst ? xf0 : xf1);

    unsigned src = (unsigned)load_idx_cs(hind, row, c.is64);
    src = min(src, (unsigned)(NH - 1));

    float4 aR, aI;

    if ((int)src < N) {
        aR = make_float4(0.f, 0.f, 0.f, 0.f);
        aI = make_float4(0.f, 0.f, 0.f, 0.f);
        #pragma unroll
        for (int k = 0; k < K_NB; ++k) {
            int off = k * N + (int)src;
            unsigned idx = (unsigned)load_idx_cs(NIp, off, c.is64);
            idx = min(idx, (unsigned)(Mrows - 1));
            float wr = __ldcs(wR + off);
            float wi = __ldcs(wI + off);
            // table gathers: default policy -> stay resident in L2
            float4 xr = __ldg(XfR + (long long)idx * 4 + t);
            float4 xi = __ldg(XfI + (long long)idx * 4 + t);
            aR.x = fmaf(wr, xr.x, fmaf(-wi, xi.x, aR.x));
            aR.y = fmaf(wr, xr.y, fmaf(-wi, xi.y, aR.y));
            aR.z = fmaf(wr, xr.z, fmaf(-wi, xi.z, aR.z));
            aR.w = fmaf(wr, xr.w, fmaf(-wi, xi.w, aR.w));
            aI.x = fmaf(wr, xi.x, fmaf(wi, xr.x, aI.x));
            aI.y = fmaf(wr, xi.y, fmaf(wi, xr.y, aI.y));
            aI.z = fmaf(wr, xi.z, fmaf(wi, xr.z, aI.z));
            aI.w = fmaf(wr, xi.w, fmaf(wi, xr.w, aI.w));
        }
    } else {
        unsigned hoff = min((unsigned)((int)src - N), (unsigned)(H - 1));
        unsigned idx = (unsigned)load_idx_cs(hmask, (int)hoff, c.is64);
        idx = min(idx, (unsigned)(Mrows - 1));
        aR = __ldg(XfR + (long long)idx * 4 + t);
        aI = __ldg(XfI + (long long)idx * 4 + t);
    }

    // ---- output: layout chosen by out_size; evict-first stores; bounded ----
    long long needF = (long long)NH * 32;
    int maxF4 = out_count >> 2;

    if ((long long)out_count >= needF) {
        float4 o0 = make_float4(aR.x, aI.x, aR.y, aI.y);
        float4 o1 = make_float4(aR.z, aI.z, aR.w, aI.w);
        int ob = row * 8 + t * 2;
        if (ob + 1 < maxF4) {
            __stcs(out + ob,     o0);
            __stcs(out + ob + 1, o1);
        }
    } else {
        int ob = row * 4 + t;
        if (ob < maxF4) __stcs(out + ob, aR);
    }
}

extern "C" void kernel_launch(void* const* d_in, const int* in_sizes, int n_in,
                              void* d_out, int out_size) {
    int smax = 0;
    for (int i = 0; i < n_in; ++i) if (in_sizes[i] > smax) smax = in_sizes[i];

    int smid = 0;
    for (int i = 0; i < n_in && !smid; ++i) {
        int s = in_sizes[i];
        if (s == smax || s <= 64) continue;
        int cnt = 0;
        for (int j = 0; j < n_in; ++j) if (in_sizes[j] == s) cnt++;
        if (cnt == 3) smid = s;
    }

    const float* xf[2] = { 0, 0 }; int nx = 0;
    const void*  mid[3] = { 0, 0, 0 }; int nm = 0;
    int hiPos = -1, hmPos = -1;
    if (smid) {
        for (int i = 0; i < n_in; ++i) {
            int s = in_sizes[i];
            if (s == smax)      { if (nx < 2) xf[nx++] = (const float*)d_in[i]; }
            else if (s == smid) { if (nm < 3) mid[nm++] = d_in[i]; }
            else if (s > 64) {
                if (hiPos < 0) hiPos = i;
                else if (s > in_sizes[hiPos]) { hmPos = hiPos; hiPos = i; }
                else hmPos = i;
            }
        }
    } else {
        int s2 = 0;
        for (int i = 0; i < n_in && !s2; ++i) {
            int s = in_sizes[i];
            if (s == smax || s <= 64) continue;
            int cnt = 0;
            for (int j = 0; j < n_in; ++j) if (in_sizes[j] == s) cnt++;
            if (cnt == 2) s2 = s;
        }
        smid = s2;
        int niPos = -1;
        for (int i = 0; i < n_in; ++i) if (in_sizes[i] == 2 * s2) niPos = i;
        int order[3], no = 0;
        for (int i = 0; i < n_in && no < 3; ++i)
            if (in_sizes[i] == s2 || i == niPos) order[no++] = i;
        for (int q = 0; q < 3; ++q) mid[q] = d_in[order[q]];
        for (int i = 0; i < n_in; ++i) {
            int s = in_sizes[i];
            if (s == smax) { if (nx < 2) xf[nx++] = (const float*)d_in[i]; }
            else if (s > 64 && s != s2 && i != niPos) {
                if (hiPos < 0) hiPos = i;
                else if (s > in_sizes[hiPos]) { hmPos = hiPos; hiPos = i; }
                else hmPos = i;
            }
        }
    }

    int s_hi = in_sizes[hiPos];
    int s_hm = in_sizes[hmPos];

    detect_kernel<<<1, 32>>>((const unsigned*)mid[0], (const unsigned*)mid[1],
                             (const unsigned*)mid[2], (const unsigned*)d_in[hiPos],
                             smid, s_hi);

    long long rows_max = s_hi;   // worst case; excess threads exit
    long long total_threads = rows_max * 4;
    int block = 256;
    long long grid = (total_threads + block - 1) / block;

    gnn_fourier_kernel<<<(int)grid, block>>>(xf[0], xf[1], mid[0], mid[1], mid[2],
                                             d_in[hmPos], d_in[hiPos],
                                             (float4*)d_out,
                                             smax, smid, s_hi, s_hm, out_size);
}

// round 6
// speedup vs baseline: 1.2320x; 1.2320x over previous
#include <cuda_runtime.h>

// gnn_42460046688469 — Fourier-graph gather + complex weighted aggregate + permuted scatter.
//
// R6: REPACK-TO-INTERLEAVED SCRATCH.
// Measured DRAM traffic (1.85-2.05 GB/launch) is ~2.3x the algorithmic floor
// (~0.8 GB). Cause: each gather reads 64B from Xf_real and 64B from Xf_imag —
// two HALF-USED 128B lines. Fix: per launch, repack Xf into a __device__
// scratch table with interleaved complex rows (128B = one L2 line per row),
// then gather single full lines. Repack is streaming/coalesced (~268 MB,
// ~40us) and runs every launch (determinism). Cache-policy hints from R5
// reverted (measured neutral-negative).
//
// Interface handling (proven in R4/R5): content-based detection of operand
// order / index width / size units; every gathered index clamped; output
// layout (interleaved complex vs real-only) chosen from out_size; all stores
// bounded by out_size.

#define K_NB 8

struct Cfg { int u; int is64; int niSel; int imagFirst; };
__device__ Cfg g_cfg;

// Interleaved-complex Xf table: up to 1,048,576 rows x 8 float4 (134 MB).
__device__ __align__(16) float4 g_scratch[8388608];

__global__ void detect_kernel(const unsigned* __restrict__ m0,
                              const unsigned* __restrict__ m1,
                              const unsigned* __restrict__ m2,
                              const unsigned* __restrict__ hind,
                              int s_mid, int s_hi)
{
    if (threadIdx.x != 0 || blockIdx.x != 0) return;

    int Wm = s_mid >> 2;   // words provably in-bounds under both unit schemes
    int Wh = s_hi >> 2;

    const unsigned* ms[3] = { m0, m1, m2 };
    int isInt[3];
    {
        int step = Wm / 67; if (step < 1) step = 1;
        for (int b = 0; b < 3; ++b) {
            int ok = 1;
            for (int j = 0; j < 64; ++j) {
                unsigned v = ms[b][(j * step + j) % Wm];
                if (v >= 0x01000000u) { ok = 0; break; }
            }
            isInt[b] = ok;
        }
    }
    int niSel = 2;
    if (isInt[0] && !isInt[2]) niSel = 0;
    else if (isInt[1] && !isInt[0] && !isInt[2]) niSel = 1;
    int imagFirst = (niSel == 0) ? 1 : 0;

    int zeros = 0;
    {
        int step = Wh / 67; if (step < 1) step = 1;
        for (int j = 0; j < 64; ++j) {
            int w = ((j * step + j) % Wh) | 1;
            if (hind[w] == 0u) zeros++;
        }
    }
    int is64 = (zeros >= 48) ? 1 : 0;

    unsigned vmax = 0;
    {
        int step = Wh / 67; if (step < 1) step = 1;
        for (int j = 0; j < 64; ++j) {
            int w = (j * step + j) % Wh;
            if (is64) w &= ~1;
            unsigned v = hind[w];
            if (v > vmax) vmax = v;
        }
    }
    unsigned thresh = is64 ? (unsigned)(s_hi >> 3) : (unsigned)(s_hi >> 2);
    int u = (vmax >= thresh) ? 1 : 4;

    Cfg c; c.u = u; c.is64 = is64; c.niSel = niSel; c.imagFirst = imagFirst;
    g_cfg = c;
}

// Streaming repack: Xf_real/Xf_imag (split) -> interleaved complex rows.
// Thread i handles one float4-quarter of a row: reads 16B from each array,
// writes 32B interleaved. Fully coalesced both sides.
__global__ void __launch_bounds__(256) repack_kernel(
    const float* __restrict__ xf0, const float* __restrict__ xf1, int s_max)
{
    Cfg c = g_cfg;
    int Mrows = (s_max / c.u) / 16;
    int i = blockIdx.x * blockDim.x + threadIdx.x;
    if (i >= Mrows * 4) return;

    const float4* R = (const float4*)(c.imagFirst ? xf1 : xf0);
    const float4* I = (const float4*)(c.imagFirst ? xf0 : xf1);
    float4 xr = __ldg(R + i);
    float4 xi = __ldg(I + i);
    g_scratch[i * 2]     = make_float4(xr.x, xi.x, xr.y, xi.y);
    g_scratch[i * 2 + 1] = make_float4(xr.z, xi.z, xr.w, xi.w);
}

__device__ __forceinline__ int load_idx(const void* p, int off, int is64) {
    return is64 ? (int)((const long long*)p)[off] : ((const int*)p)[off];
}

__global__ void __launch_bounds__(256, 8) gnn_fourier_kernel(
    const void*  __restrict__ m0,  const void*  __restrict__ m1,
    const void*  __restrict__ m2,
    const void*  __restrict__ hmask, const void* __restrict__ hind,
    float4* __restrict__ out,
    int s_max, int s_mid, int s_hi, int s_hm, int out_count)
{
    Cfg c = g_cfg;

    int idxDiv = c.u * ((c.is64 && c.u == 4) ? 2 : 1);
    int NH     = s_hi / idxDiv;
    int H      = s_hm / idxDiv;
    int N      = (s_mid / c.u) / K_NB;
    int Mrows  = (s_max / c.u) / 16;

    int gid = blockIdx.x * blockDim.x + threadIdx.x;
    int row = gid >> 2;
    if (row >= NH) return;
    int t = gid & 3;

    const void* mids[3] = { m0, m1, m2 };
    const void* NIp = mids[c.niSel];
    const void* wa  = (c.niSel == 0) ? m1 : m0;
    const void* wb  = (c.niSel == 2) ? m1 : m2;
    const float* wR = (const float*)(c.imagFirst ? wb : wa);
    const float* wI = (const float*)(c.imagFirst ? wa : wb);

    unsigned src = (unsigned)load_idx(hind, row, c.is64);
    src = min(src, (unsigned)(NH - 1));

    const float4* S = g_scratch;
    float4 a0, a1;   // interleaved (re,im) accumulators: channels [4t, 4t+4)

    if ((int)src < N) {
        a0 = make_float4(0.f, 0.f, 0.f, 0.f);
        a1 = make_float4(0.f, 0.f, 0.f, 0.f);
        #pragma unroll
        for (int k = 0; k < K_NB; ++k) {
            int off = k * N + (int)src;
            unsigned idx = (unsigned)load_idx(NIp, off, c.is64);
            idx = min(idx, (unsigned)(Mrows - 1));
            float wr = __ldg(wR + off);
            float wi = __ldg(wI + off);
            long long base = (long long)idx * 8 + t * 2;
            float4 v0 = __ldg(S + base);
            float4 v1 = __ldg(S + base + 1);
            // (re + i*im) * (wr + i*wi), interleaved lanes
            a0.x = fmaf(wr, v0.x, fmaf(-wi, v0.y, a0.x));
            a0.y = fmaf(wr, v0.y, fmaf( wi, v0.x, a0.y));
            a0.z = fmaf(wr, v0.z, fmaf(-wi, v0.w, a0.z));
            a0.w = fmaf(wr, v0.w, fmaf( wi, v0.z, a0.w));
            a1.x = fmaf(wr, v1.x, fmaf(-wi, v1.y, a1.x));
            a1.y = fmaf(wr, v1.y, fmaf( wi, v1.x, a1.y));
            a1.z = fmaf(wr, v1.z, fmaf(-wi, v1.w, a1.z));
            a1.w = fmaf(wr, v1.w, fmaf( wi, v1.z, a1.w));
        }
    } else {
        unsigned hoff = min((unsigned)((int)src - N), (unsigned)(H - 1));
        unsigned idx = (unsigned)load_idx(hmask, (int)hoff, c.is64);
        idx = min(idx, (unsigned)(Mrows - 1));
        long long base = (long long)idx * 8 + t * 2;
        a0 = __ldg(S + base);
        a1 = __ldg(S + base + 1);
    }

    // ---- output: layout chosen by out_size; every store bounded ----
    long long needF = (long long)NH * 32;
    int maxF4 = out_count >> 2;

    if ((long long)out_count >= needF) {
        // interleaved complex view: accumulators are already in layout
        int ob = row * 8 + t * 2;
        if (ob + 1 < maxF4) {
            out[ob]     = a0;
            out[ob + 1] = a1;
        }
    } else {
        // real part only
        int ob = row * 4 + t;
        if (ob < maxF4) out[ob] = make_float4(a0.x, a0.z, a1.x, a1.z);
    }
}

extern "C" void kernel_launch(void* const* d_in, const int* in_sizes, int n_in,
                              void* d_out, int out_size) {
    int smax = 0;
    for (int i = 0; i < n_in; ++i) if (in_sizes[i] > smax) smax = in_sizes[i];

    int smid = 0;
    for (int i = 0; i < n_in && !smid; ++i) {
        int s = in_sizes[i];
        if (s == smax || s <= 64) continue;
        int cnt = 0;
        for (int j = 0; j < n_in; ++j) if (in_sizes[j] == s) cnt++;
        if (cnt == 3) smid = s;
    }

    const float* xf[2] = { 0, 0 }; int nx = 0;
    const void*  mid[3] = { 0, 0, 0 }; int nm = 0;
    int hiPos = -1, hmPos = -1;
    if (smid) {
        for (int i = 0; i < n_in; ++i) {
            int s = in_sizes[i];
            if (s == smax)      { if (nx < 2) xf[nx++] = (const float*)d_in[i]; }
            else if (s == smid) { if (nm < 3) mid[nm++] = d_in[i]; }
            else if (s > 64) {
                if (hiPos < 0) hiPos = i;
                else if (s > in_sizes[hiPos]) { hmPos = hiPos; hiPos = i; }
                else hmPos = i;
            }
        }
    } else {
        int s2 = 0;
        for (int i = 0; i < n_in && !s2; ++i) {
            int s = in_sizes[i];
            if (s == smax || s <= 64) continue;
            int cnt = 0;
            for (int j = 0; j < n_in; ++j) if (in_sizes[j] == s) cnt++;
            if (cnt == 2) s2 = s;
        }
        smid = s2;
        int niPos = -1;
        for (int i = 0; i < n_in; ++i) if (in_sizes[i] == 2 * s2) niPos = i;
        int order[3], no = 0;
        for (int i = 0; i < n_in && no < 3; ++i)
            if (in_sizes[i] == s2 || i == niPos) order[no++] = i;
        for (int q = 0; q < 3; ++q) mid[q] = d_in[order[q]];
        for (int i = 0; i < n_in; ++i) {
            int s = in_sizes[i];
            if (s == smax) { if (nx < 2) xf[nx++] = (const float*)d_in[i]; }
            else if (s > 64 && s != s2 && i != niPos) {
                if (hiPos < 0) hiPos = i;
                else if (s > in_sizes[hiPos]) { hmPos = hiPos; hiPos = i; }
                else hmPos = i;
            }
        }
    }

    int s_hi = in_sizes[hiPos];
    int s_hm = in_sizes[hmPos];

    detect_kernel<<<1, 32>>>((const unsigned*)mid[0], (const unsigned*)mid[1],
                             (const unsigned*)mid[2], (const unsigned*)d_in[hiPos],
                             smid, s_hi);

    // repack: worst-case Mrows*4 threads = smax/4 (element-count hypothesis)
    {
        long long rthreads = (long long)smax / 4;
        int block = 256;
        long long rgrid = (rthreads + block - 1) / block;
        repack_kernel<<<(int)rgrid, block>>>(xf[0], xf[1], smax);
    }

    long long rows_max = s_hi;   // worst case; excess threads exit
    long long total_threads = rows_max * 4;
    int block = 256;
    long long grid = (total_threads + block - 1) / block;

    gnn_fourier_kernel<<<(int)grid, block>>>(mid[0], mid[1], mid[2],
                                             d_in[hmPos], d_in[hiPos],
                                             (float4*)d_out,
                                             smax, smid, s_hi, s_hm, out_size);
}